// round 6
// baseline (speedup 1.0000x reference)
#include <cuda_runtime.h>
#include <math_constants.h>

#define NB      64          // batches
#define HW      262144      // 512*512 per batch
#define WIDTH   512
#define CHUNKS  16
#define TPB     256
#define NBLOCKS (NB * CHUNKS)                  // 1024
#define VEC4_PER_CHUNK  (HW / CHUNKS / 4)      // 4096
#define ITERS   (VEC4_PER_CHUNK / TPB)         // 16
#define UF      2                              // 4 LDG.128 batched per group
#define GROUPS  (ITERS / UF)                   // 8

// Scratch (device globals — no allocation allowed)
__device__ float g_pmax[NBLOCKS];
__device__ int   g_pidx[NBLOCKS];
__device__ float g_lmax[NBLOCKS];
__device__ int   g_lidx[NBLOCKS];
__device__ float g_sq  [NBLOCKS];
__device__ unsigned int g_count = 0;

__device__ __forceinline__ void amax_upd(float v, int ix, float& m, int& mi) {
    if (v > m || (v == m && ix < mi)) { m = v; mi = ix; }
}

// value+pos combine; pos monotone with flat idx => exact first-occurrence argmax
__device__ __forceinline__ void vpos_upd(float v, int p, float& m, int& mp) {
    if (v > m || (v == m && p < mp)) { m = v; mp = p; }
}

__global__ void __launch_bounds__(TPB, 8) loss_fused(
    const float* __restrict__ pred, const float* __restrict__ label,
    float* __restrict__ out)
{
    const int b = blockIdx.y;
    const int c = blockIdx.x;
    const int t = threadIdx.x;
    const int base4 = c * VEC4_PER_CHUNK;

    // single base pointer per tensor; all loop loads are [base + imm]
    const float4* __restrict__ pp =
        (const float4*)(pred  + (size_t)b * HW) + base4 + t;
    const float4* __restrict__ lp =
        (const float4*)(label + (size_t)b * HW) + base4 + t;

    float pm = -CUDART_INF_F; int ppos = 0;   // pos at float4 granularity
    float lm = -CUDART_INF_F; int lpos = 0;
    float ss = 0.0f;

    #pragma unroll
    for (int g = 0; g < GROUPS; ++g) {
        // 4 LDG.128 batched, all addresses = base reg + compile-time imm
        float4 P0 = pp[(2 * g    ) * TPB];
        float4 L0 = lp[(2 * g    ) * TPB];
        float4 P1 = pp[(2 * g + 1) * TPB];
        float4 L1 = lp[(2 * g + 1) * TPB];

        {
            float d0 = P0.x - L0.x, d1 = P0.y - L0.y;
            float d2 = P0.z - L0.z, d3 = P0.w - L0.w;
            ss = fmaf(d0, d0, ss); ss = fmaf(d1, d1, ss);
            ss = fmaf(d2, d2, ss); ss = fmaf(d3, d3, ss);
            float pmax4 = fmaxf(fmaxf(P0.x, P0.y), fmaxf(P0.z, P0.w));
            if (pmax4 > pm) { pm = pmax4; ppos = (2 * g) * TPB + t; }
            float lmax4 = fmaxf(fmaxf(L0.x, L0.y), fmaxf(L0.z, L0.w));
            if (lmax4 > lm) { lm = lmax4; lpos = (2 * g) * TPB + t; }
        }
        {
            float d0 = P1.x - L1.x, d1 = P1.y - L1.y;
            float d2 = P1.z - L1.z, d3 = P1.w - L1.w;
            ss = fmaf(d0, d0, ss); ss = fmaf(d1, d1, ss);
            ss = fmaf(d2, d2, ss); ss = fmaf(d3, d3, ss);
            float pmax4 = fmaxf(fmaxf(P1.x, P1.y), fmaxf(P1.z, P1.w));
            if (pmax4 > pm) { pm = pmax4; ppos = (2 * g + 1) * TPB + t; }
            float lmax4 = fmaxf(fmaxf(L1.x, L1.y), fmaxf(L1.z, L1.w));
            if (lmax4 > lm) { lm = lmax4; lpos = (2 * g + 1) * TPB + t; }
        }
    }

    // ---- block reduction: warp shuffles, then cross-warp via smem ----
    const unsigned FULL = 0xffffffffu;
    #pragma unroll
    for (int off = 16; off > 0; off >>= 1) {
        float v; int p;
        v = __shfl_down_sync(FULL, pm, off); p = __shfl_down_sync(FULL, ppos, off);
        vpos_upd(v, p, pm, ppos);
        v = __shfl_down_sync(FULL, lm, off); p = __shfl_down_sync(FULL, lpos, off);
        vpos_upd(v, p, lm, lpos);
        ss += __shfl_down_sync(FULL, ss, off);
    }

    __shared__ float wpm[8]; __shared__ int wpp[8];
    __shared__ float wlm[8]; __shared__ int wlp[8];
    __shared__ float wss[8];
    const int warp = t >> 5, lane = t & 31;
    if (lane == 0) {
        wpm[warp] = pm; wpp[warp] = ppos;
        wlm[warp] = lm; wlp[warp] = lpos;
        wss[warp] = ss;
    }
    __syncthreads();

    __shared__ bool is_last;
    if (t == 0) {
        float bpm = wpm[0]; int bpp = wpp[0];
        float blm = wlm[0]; int blp = wlp[0];
        float bss = wss[0];
        #pragma unroll
        for (int w = 1; w < 8; ++w) {
            vpos_upd(wpm[w], wpp[w], bpm, bpp);
            vpos_upd(wlm[w], wlp[w], blm, blp);
            bss += wss[w];
        }
        // recover exact element index: reload the two winning float4s
        const float4* pb = (const float4*)(pred  + (size_t)b * HW) + base4;
        const float4* lb = (const float4*)(label + (size_t)b * HW) + base4;
        const float4 Pw = pb[bpp];
        const float4 Lw = lb[blp];
        int pj = 3;
        if (Pw.w == bpm) pj = 3; if (Pw.z == bpm) pj = 2;
        if (Pw.y == bpm) pj = 1; if (Pw.x == bpm) pj = 0;
        int lj = 3;
        if (Lw.w == blm) lj = 3; if (Lw.z == blm) lj = 2;
        if (Lw.y == blm) lj = 1; if (Lw.x == blm) lj = 0;

        const int o = b * CHUNKS + c;
        g_pmax[o] = bpm; g_pidx[o] = (base4 + bpp) * 4 + pj;
        g_lmax[o] = blm; g_lidx[o] = (base4 + blp) * 4 + lj;
        g_sq[o]   = bss;
        __threadfence();
        unsigned int n = atomicAdd(&g_count, 1u);
        is_last = (n == NBLOCKS - 1);
    }
    __syncthreads();
    if (!is_last) return;

    // ---- final reduction (partials are L2-hot) ----
    {
        const int fb = t >> 2;        // batch 0..63
        const int cg = t & 3;         // chunk group 0..3

        float fpm = -CUDART_INF_F; int fpi = 0;
        float flm = -CUDART_INF_F; int fli = 0;
        float fss = 0.0f;

        #pragma unroll
        for (int k = 0; k < 4; ++k) {
            const int o = fb * CHUNKS + cg * 4 + k;
            amax_upd(g_pmax[o], g_pidx[o], fpm, fpi);
            amax_upd(g_lmax[o], g_lidx[o], flm, fli);
            fss += g_sq[o];
        }

        #pragma unroll
        for (int off = 2; off > 0; off >>= 1) {
            float v  = __shfl_down_sync(FULL, fpm, off, 4);
            int   ix = __shfl_down_sync(FULL, fpi, off, 4);
            amax_upd(v, ix, fpm, fpi);
            v  = __shfl_down_sync(FULL, flm, off, 4);
            ix = __shfl_down_sync(FULL, fli, off, 4);
            amax_upd(v, ix, flm, fli);
            fss += __shfl_down_sync(FULL, fss, off, 4);
        }

        __shared__ float sidx[64];
        __shared__ float smse[64];
        if (cg == 0) {
            const float rp = (float)(fpi / WIDTH), cp = (float)(fpi % WIDTH);
            const float rl = (float)(fli / WIDTH), cl = (float)(fli % WIDTH);
            const float dr = rp - rl, dc = cp - cl;
            sidx[fb] = dr * dr + dc * dc;
            smse[fb] = fss;
        }
        __syncthreads();

        if (t < 32) {
            float I = sidx[t] + sidx[t + 32];
            float M = smse[t] + smse[t + 32];
            #pragma unroll
            for (int off = 16; off > 0; off >>= 1) {
                I += __shfl_down_sync(FULL, I, off);
                M += __shfl_down_sync(FULL, M, off);
            }
            if (t == 0) {
                const float alpha = (I != 0.0f) ? (M / I) : 1.0f;
                out[0] = (M + 0.25f * alpha * I) / (float)NB;
                g_count = 0;  // reset for next graph replay
            }
        }
    }
}

extern "C" void kernel_launch(void* const* d_in, const int* in_sizes, int n_in,
                              void* d_out, int out_size)
{
    const float* pred  = (const float*)d_in[0];
    const float* label = (const float*)d_in[1];
    float* out = (float*)d_out;

    dim3 grid(CHUNKS, NB);
    loss_fused<<<grid, TPB>>>(pred, label, out);
}